// round 9
// baseline (speedup 1.0000x reference)
#include <cuda_runtime.h>
#include <cuda_bf16.h>
#include <cstdint>

// ---------------------------------------------------------------------------
// B=4, C=512, C8=64, N=4096 — all GEMMs on HMMA (mma.sync bf16, fp32 accum)
// 0) convert: xb=bf16(x), Wfgb=bf16([Wf;Wg]), Whb=bf16(Wh), bias pack
// 1) fg = Wfgb@xb + bfg  (HMMA 128-tile, bf16: rows 0-63 = f, 64-127 = g)
//    hv = Whb @xb + bh   (HMMA 256x128-tile, bf16)
// 2) fT = transpose(f)
// 3) flash-style split softmax over j-quarters (no fp32 logits buffer):
//    pass1 (512 CTAs): online (m,Z) per row per j-quarter -> partial stats
//    combine: merge 4 partials per row -> (M, 1/Z)
//    pass2 (512 CTAs): recompute logits, write bf16 attn
// 4) out = gamma * (hv @ attn) + x   (HMMA 256x128-tile, fused epilogue)
// NOTE: tcgen05 unavailable (toolchain targets compute_103 w/o 'a' features).
// ---------------------------------------------------------------------------

#define BATCH 4
#define NC    512
#define NC8   64
#define NTOK  4096

__device__ __nv_bfloat16  d_xb    [(long)BATCH * NC  * NTOK];     //  16 MB
__device__ __nv_bfloat16  d_Wfgb  [(long)2 * NC8 * NC];           // 128 KB
__device__ __nv_bfloat16  d_Whb   [(long)NC * NC];                // 512 KB
__device__ float          d_bfg   [2 * NC8];
__device__ __nv_bfloat16  d_fgb   [(long)BATCH * 2 * NC8 * NTOK]; //   8 MB
__device__ __nv_bfloat16  d_fTb   [(long)BATCH * NTOK * NC8];     //   4 MB
__device__ __nv_bfloat16  d_hvb   [(long)BATCH * NC  * NTOK];     //  16 MB
__device__ __nv_bfloat16  d_attnb [(long)BATCH * NTOK * NTOK];    // 128 MB
__device__ float2         d_statsP[(long)BATCH * 4 * NTOK];       // 512 KB
__device__ float2         d_statsF[(long)BATCH * NTOK];           // 128 KB

// ===========================================================================
// small helpers
// ===========================================================================
__device__ __forceinline__ uint32_t smem_u32(const void* p) {
    uint32_t a;
    asm("{ .reg .u64 t; cvta.to.shared.u64 t, %1; cvt.u32.u64 %0, t; }"
        : "=r"(a) : "l"(p));
    return a;
}
__device__ __forceinline__ void cp16(uint32_t s, const void* g) {
    asm volatile("cp.async.cg.shared.global [%0], [%1], 16;" :: "r"(s), "l"(g));
}
__device__ __forceinline__ void ldsm_x4(uint32_t* r, uint32_t a) {
    asm volatile("ldmatrix.sync.aligned.m8n8.x4.shared.b16 {%0,%1,%2,%3}, [%4];"
                 : "=r"(r[0]), "=r"(r[1]), "=r"(r[2]), "=r"(r[3]) : "r"(a));
}
__device__ __forceinline__ void ldsm_x2_t(uint32_t* r, uint32_t a) {
    asm volatile("ldmatrix.sync.aligned.m8n8.x2.trans.shared.b16 {%0,%1}, [%2];"
                 : "=r"(r[0]), "=r"(r[1]) : "r"(a));
}
__device__ __forceinline__ void mma_bf16(float* d, const uint32_t* a, const uint32_t* b) {
    asm volatile(
        "mma.sync.aligned.m16n8k16.row.col.f32.bf16.bf16.f32 "
        "{%0,%1,%2,%3}, {%4,%5,%6,%7}, {%8,%9}, {%0,%1,%2,%3};"
        : "+f"(d[0]), "+f"(d[1]), "+f"(d[2]), "+f"(d[3])
        : "r"(a[0]), "r"(a[1]), "r"(a[2]), "r"(a[3]), "r"(b[0]), "r"(b[1]));
}
__device__ __forceinline__ float qmax4(float v) {
    v = fmaxf(v, __shfl_xor_sync(0xffffffffu, v, 1));
    v = fmaxf(v, __shfl_xor_sync(0xffffffffu, v, 2));
    return v;
}
__device__ __forceinline__ float qsum4(float v) {
    v += __shfl_xor_sync(0xffffffffu, v, 1);
    v += __shfl_xor_sync(0xffffffffu, v, 2);
    return v;
}

// ===========================================================================
// fp32 -> bf16 convert (vectorized) + bias pack
// ===========================================================================
__global__ __launch_bounds__(256) void f32_to_bf16(
    const float* __restrict__ in, __nv_bfloat16* __restrict__ out, long n4)
{
    long i = (long)blockIdx.x * 256 + threadIdx.x;
    if (i >= n4) return;
    float4 v = ((const float4*)in)[i];
    __nv_bfloat162 p[2];
    p[0] = __floats2bfloat162_rn(v.x, v.y);
    p[1] = __floats2bfloat162_rn(v.z, v.w);
    ((uint2*)out)[i] = *(uint2*)p;
}

__global__ __launch_bounds__(128) void pack_bias(
    const float* __restrict__ bf, const float* __restrict__ bg,
    float* __restrict__ bfg)
{
    int t = threadIdx.x;
    bfg[t] = (t < NC8) ? bf[t] : bg[t - NC8];
}

// ===========================================================================
// bf16 64x64-tile transpose: fT[n, o] = f[o, n]
// ===========================================================================
__global__ __launch_bounds__(256) void transpose_f(
    const __nv_bfloat16* __restrict__ in, long sIn,
    __nv_bfloat16* __restrict__ outp)
{
    __shared__ __nv_bfloat16 t[64][72];
    const __nv_bfloat16* ip = in + (long)blockIdx.z * sIn;
    __nv_bfloat16* op = outp + (long)blockIdx.z * NTOK * NC8;
    const int j0 = blockIdx.x * 64;
    const int tid = threadIdx.x;

    #pragma unroll
    for (int pass = 0; pass < 4; pass++) {
        int v = tid + pass * 256;
        int r = v >> 4, c4 = v & 15;
        uint2 d = *(const uint2*)(ip + (long)r * NTOK + j0 + c4 * 4);
        *(uint2*)&t[r][c4 * 4] = d;
    }
    __syncthreads();
    #pragma unroll
    for (int pass = 0; pass < 4; pass++) {
        int v = tid + pass * 256;
        int r = v >> 4, c4 = v & 15;
        __nv_bfloat16 tmp[4];
        tmp[0] = t[c4 * 4 + 0][r];
        tmp[1] = t[c4 * 4 + 1][r];
        tmp[2] = t[c4 * 4 + 2][r];
        tmp[3] = t[c4 * 4 + 3][r];
        *(uint2*)(op + (long)(j0 + r) * NC8 + c4 * 4) = *(uint2*)tmp;
    }
}

// ===========================================================================
// Flash-split logits+softmax.
// Grid (NTOK/128, 4 j-quarters, BATCH). Each CTA: 128 rows x 1024 cols.
// PASS 1: online row (m, Z) over its 8 j-tiles -> statsP[b][jq][row]
// PASS 2: read combined stats (M, 1/Z), recompute logits, write bf16 attn
// ===========================================================================

#define LS_SMEM_AF   0
#define LS_SMEM_BS   18432                  // Af: 128*72*2
#define LS_SMEM_RED  (LS_SMEM_BS + 34816)   // Bs: 2*64*136*2
#define LS_SMEM_MRUN (LS_SMEM_RED + 2048)
#define LS_SMEM_ZRUN (LS_SMEM_MRUN + 512)
#define LS_SMEM_MT   (LS_SMEM_ZRUN + 512)
#define LS_SMEM_TOT  (LS_SMEM_MT + 512)     // 56832 B

template<int PASS>
__global__ __launch_bounds__(256) void logits_pass(
    const __nv_bfloat16* __restrict__ fT,
    const __nv_bfloat16* __restrict__ gmat, long sG,
    float2* __restrict__ statsP,
    const float2* __restrict__ statsF,
    __nv_bfloat16* __restrict__ attn)
{
    extern __shared__ char sm[];
    __nv_bfloat16 (*Af)[72]      = (__nv_bfloat16(*)[72])(sm + LS_SMEM_AF);
    __nv_bfloat16 (*Bs)[64][136] = (__nv_bfloat16(*)[64][136])(sm + LS_SMEM_BS);
    float (*red)[4] = (float(*)[4])(sm + LS_SMEM_RED);
    float* mrun = (float*)(sm + LS_SMEM_MRUN);
    float* zrun = (float*)(sm + LS_SMEM_ZRUN);
    float* mt   = (float*)(sm + LS_SMEM_MT);

    const int b  = blockIdx.z;
    const int jq = blockIdx.y;
    const int m0 = blockIdx.x * 128;
    const long jbase = (long)jq * 1024;

    fT   += (long)b * NTOK * NC8;
    gmat += (long)b * sG + jbase;
    attn += (long)b * NTOK * NTOK + (long)m0 * NTOK + jbase;

    const int tid  = threadIdx.x;
    const int wid  = tid >> 5;
    const int lane = tid & 31;
    const int wm   = (wid >> 2) * 64;
    const int wn   = (wid & 3) * 32;
    const int wcol = wid & 3;
    const int rbase = lane >> 2;
    const int cbase = (lane & 3) * 2;

    // --- prologue loads ---
    #pragma unroll
    for (int p = 0; p < 4; p++) {
        int seg = tid * 4 + p;
        int r = seg >> 3, sc = seg & 7;
        cp16(smem_u32(&Af[r][sc * 8]), fT + (long)(m0 + r) * NC8 + sc * 8);
    }
    asm volatile("cp.async.commit_group;");
    #pragma unroll
    for (int p = 0; p < 4; p++) {
        int seg = tid * 4 + p;
        int r = seg >> 4, sc = seg & 15;
        cp16(smem_u32(&Bs[0][r][sc * 8]), gmat + (long)r * NTOK + sc * 8);
    }
    asm volatile("cp.async.commit_group;");

    if (PASS == 1) {
        if (tid < 128) { mrun[tid] = -1e30f; zrun[tid] = 0.f; }
    } else {
        if (tid < 128) {
            float2 s = statsF[(long)b * NTOK + m0 + tid];
            mrun[tid] = s.x;   // M
            zrun[tid] = s.y;   // 1/Z
        }
    }

    asm volatile("cp.async.wait_group 0;");
    __syncthreads();

    // --- hoist A fragments ---
    uint32_t af[4][4][4];
    #pragma unroll
    for (int kk = 0; kk < 4; kk++)
        #pragma unroll
        for (int mi = 0; mi < 4; mi++)
            ldsm_x4(af[kk][mi], smem_u32(
                &Af[wm + mi * 16 + (lane & 15)][kk * 16 + ((lane >> 4) & 1) * 8]));

    auto load_b = [&](int st, int jt) {
        const __nv_bfloat16* gp = gmat + jt * 128;
        #pragma unroll
        for (int p = 0; p < 4; p++) {
            int seg = tid * 4 + p;
            int r = seg >> 4, sc = seg & 15;
            cp16(smem_u32(&Bs[st][r][sc * 8]), gp + (long)r * NTOK + sc * 8);
        }
        asm volatile("cp.async.commit_group;");
    };

    for (int jt = 0; jt < 8; jt++) {
        const int st = jt & 1;
        if (jt + 1 < 8) {
            load_b(st ^ 1, jt + 1);
            asm volatile("cp.async.wait_group 1;");
        } else {
            asm volatile("cp.async.wait_group 0;");
        }
        __syncthreads();

        float acc[4][4][4];
        #pragma unroll
        for (int mi = 0; mi < 4; mi++)
            #pragma unroll
            for (int ni = 0; ni < 4; ni++)
                #pragma unroll
                for (int r = 0; r < 4; r++) acc[mi][ni][r] = 0.f;
        #pragma unroll
        for (int kk = 0; kk < 4; kk++) {
            uint32_t bfr[4][2];
            #pragma unroll
            for (int ni = 0; ni < 4; ni++)
                ldsm_x2_t(bfr[ni], smem_u32(
                    &Bs[st][kk * 16 + (lane & 15)][wn + ni * 8]));
            #pragma unroll
            for (int mi = 0; mi < 4; mi++)
                #pragma unroll
                for (int ni = 0; ni < 4; ni++)
                    mma_bf16(acc[mi][ni], af[kk][mi], bfr[ni]);
        }

        if (PASS == 1) {
            // per-row tile max
            #pragma unroll
            for (int mi = 0; mi < 4; mi++) {
                float lo = -1e30f, hi = -1e30f;
                #pragma unroll
                for (int ni = 0; ni < 4; ni++) {
                    lo = fmaxf(lo, fmaxf(acc[mi][ni][0], acc[mi][ni][1]));
                    hi = fmaxf(hi, fmaxf(acc[mi][ni][2], acc[mi][ni][3]));
                }
                lo = qmax4(lo);
                hi = qmax4(hi);
                if ((lane & 3) == 0) {
                    red[wm + mi * 16 + rbase][wcol]     = lo;
                    red[wm + mi * 16 + 8 + rbase][wcol] = hi;
                }
            }
            __syncthreads();
            if (tid < 128) {
                float t = fmaxf(fmaxf(red[tid][0], red[tid][1]),
                                fmaxf(red[tid][2], red[tid][3]));
                mt[tid] = fmaxf(mrun[tid], t);
            }
            __syncthreads();

            // per-row exp-sum vs new max
            #pragma unroll
            for (int mi = 0; mi < 4; mi++) {
                const int rlo = wm + mi * 16 + rbase, rhi = rlo + 8;
                const float mlo = mt[rlo], mhi = mt[rhi];
                float slo = 0.f, shi = 0.f;
                #pragma unroll
                for (int ni = 0; ni < 4; ni++) {
                    slo += __expf(acc[mi][ni][0] - mlo) + __expf(acc[mi][ni][1] - mlo);
                    shi += __expf(acc[mi][ni][2] - mhi) + __expf(acc[mi][ni][3] - mhi);
                }
                slo = qsum4(slo);
                shi = qsum4(shi);
                if ((lane & 3) == 0) {
                    red[rlo][wcol] = slo;
                    red[rhi][wcol] = shi;
                }
            }
            __syncthreads();
            if (tid < 128) {
                float s = red[tid][0] + red[tid][1] + red[tid][2] + red[tid][3];
                zrun[tid] = zrun[tid] * __expf(mrun[tid] - mt[tid]) + s;
                mrun[tid] = mt[tid];
            }
            __syncthreads();
        } else {
            #pragma unroll
            for (int mi = 0; mi < 4; mi++) {
                const int rlo = wm + mi * 16 + rbase, rhi = rlo + 8;
                const float mlo = mrun[rlo], ilo = zrun[rlo];
                const float mhi = mrun[rhi], ihi = zrun[rhi];
                #pragma unroll
                for (int ni = 0; ni < 4; ni++) {
                    const long col = (long)jt * 128 + wn + ni * 8 + cbase;
                    float p0 = __expf(acc[mi][ni][0] - mlo) * ilo;
                    float p1 = __expf(acc[mi][ni][1] - mlo) * ilo;
                    float p2 = __expf(acc[mi][ni][2] - mhi) * ihi;
                    float p3 = __expf(acc[mi][ni][3] - mhi) * ihi;
                    *(__nv_bfloat162*)&attn[(long)rlo * NTOK + col] =
                        __floats2bfloat162_rn(p0, p1);
                    *(__nv_bfloat162*)&attn[(long)rhi * NTOK + col] =
                        __floats2bfloat162_rn(p2, p3);
                }
            }
            __syncthreads();   // protect Bs[st] before refill
        }
    }

    if (PASS == 1 && tid < 128) {
        statsP[((long)b * 4 + jq) * NTOK + m0 + tid] =
            make_float2(mrun[tid], zrun[tid]);
    }
}

// combine 4 j-quarter partials per row -> (M, 1/Z)
__global__ __launch_bounds__(256) void stats_combine(
    const float2* __restrict__ part, float2* __restrict__ fin)
{
    const int idx = blockIdx.x * 256 + threadIdx.x;   // b*NTOK + row
    const int b = idx >> 12, row = idx & (NTOK - 1);
    float2 q0 = part[((long)b * 4 + 0) * NTOK + row];
    float2 q1 = part[((long)b * 4 + 1) * NTOK + row];
    float2 q2 = part[((long)b * 4 + 2) * NTOK + row];
    float2 q3 = part[((long)b * 4 + 3) * NTOK + row];
    float M = fmaxf(fmaxf(q0.x, q1.x), fmaxf(q2.x, q3.x));
    float Z = q0.y * __expf(q0.x - M) + q1.y * __expf(q1.x - M)
            + q2.y * __expf(q2.x - M) + q3.y * __expf(q3.x - M);
    fin[idx] = make_float2(M, 1.0f / Z);
}

// ===========================================================================
// bf16 HMMA GEMM, 128x128x32 tiles (for the small fg projection, M=128)
// EPI=0: C(bf16) = acc + bias[m]
// ===========================================================================

#define ALD  40
#define BLD  136

__global__ __launch_bounds__(256) void gemm_mma_fg(
    const __nv_bfloat16* __restrict__ A, int ldA,
    const __nv_bfloat16* __restrict__ B, long sB, int ldB,
    __nv_bfloat16* __restrict__ Cb, long sC, int ldC,
    const float* __restrict__ bias, int K)
{
    __shared__ __nv_bfloat16 As[2][128][ALD];
    __shared__ __nv_bfloat16 Bs[2][32][BLD];

    const int b  = blockIdx.z;
    const int n0 = blockIdx.x * 128;
    B  += (long)b * sB;
    Cb += (long)b * sC;

    const int tid  = threadIdx.x;
    const int wid  = tid >> 5;
    const int lane = tid & 31;
    const int wm   = (wid >> 2) * 64;
    const int wn   = (wid & 3) * 32;

    float acc[4][4][4];
    #pragma unroll
    for (int i = 0; i < 4; i++)
        #pragma unroll
        for (int j = 0; j < 4; j++)
            #pragma unroll
            for (int r = 0; r < 4; r++) acc[i][j][r] = 0.f;

    auto load_stage = [&](int st, int k0) {
        #pragma unroll
        for (int p = 0; p < 2; p++) {
            int seg = tid * 2 + p;
            int r = seg >> 2, sc = seg & 3;
            cp16(smem_u32(&As[st][r][sc * 8]), A + (long)r * ldA + k0 + sc * 8);
        }
        #pragma unroll
        for (int p = 0; p < 2; p++) {
            int seg = tid * 2 + p;
            int r = seg >> 4, sc = seg & 15;
            cp16(smem_u32(&Bs[st][r][sc * 8]), B + (long)(k0 + r) * ldB + n0 + sc * 8);
        }
        asm volatile("cp.async.commit_group;");
    };

    const int KT = K >> 5;
    load_stage(0, 0);

    for (int kt = 0; kt < KT; kt++) {
        const int st = kt & 1;
        if (kt + 1 < KT) {
            load_stage(st ^ 1, (kt + 1) * 32);
            asm volatile("cp.async.wait_group 1;");
        } else {
            asm volatile("cp.async.wait_group 0;");
        }
        __syncthreads();

        #pragma unroll
        for (int kk = 0; kk < 2; kk++) {
            uint32_t af[4][4];
            #pragma unroll
            for (int mi = 0; mi < 4; mi++)
                ldsm_x4(af[mi], smem_u32(
                    &As[st][wm + mi * 16 + (lane & 15)][kk * 16 + ((lane >> 4) & 1) * 8]));
            uint32_t bf[4][2];
            #pragma unroll
            for (int ni = 0; ni < 4; ni++)
                ldsm_x2_t(bf[ni], smem_u32(
                    &Bs[st][kk * 16 + (lane & 15)][wn + ni * 8]));
            #pragma unroll
            for (int mi = 0; mi < 4; mi++)
                #pragma unroll
                for (int ni = 0; ni < 4; ni++)
                    mma_bf16(acc[mi][ni], af[mi], bf[ni]);
        }
        __syncthreads();
    }

    const int rbase = lane >> 2;
    const int cbase = (lane & 3) * 2;
    #pragma unroll
    for (int mi = 0; mi < 4; mi++) {
        #pragma unroll
        for (int ni = 0; ni < 4; ni++) {
            int row = wm + mi * 16 + rbase;
            int col = n0 + wn + ni * 8 + cbase;
            float bv0 = bias[row], bv1 = bias[row + 8];
            *(__nv_bfloat162*)&Cb[(long)row * ldC + col] =
                __floats2bfloat162_rn(acc[mi][ni][0] + bv0, acc[mi][ni][1] + bv0);
            *(__nv_bfloat162*)&Cb[(long)(row + 8) * ldC + col] =
                __floats2bfloat162_rn(acc[mi][ni][2] + bv1, acc[mi][ni][3] + bv1);
        }
    }
}

// ===========================================================================
// bf16 HMMA GEMM, 256x128x32 tiles, 256 threads, 8 warps at 64x64 warptiles.
// EPI=0: C(bf16) = acc + bias[m];  EPI=2: C(f32) = gamma[0]*acc + resid[m,n]
// Dynamic smem: As 2 x 256x40, Bs 2 x 32x136 (58368 B)
// ===========================================================================

#define BG_AS_STG 20480u
#define BG_BS_OFF 40960u
#define BG_BS_STG 8704u
#define BG_SMEM_TOT 58368

template<int EPI>
__global__ __launch_bounds__(256) void gemm_mma_big(
    const __nv_bfloat16* __restrict__ A, long sA, int ldA,
    const __nv_bfloat16* __restrict__ B, long sB, int ldB,
    void*                __restrict__ Cv, long sC, int ldC,
    const float* __restrict__ bias,
    const float* __restrict__ resid, long sR,
    const float* __restrict__ gamma,
    int K)
{
    extern __shared__ char sm[];
    const uint32_t sbase = smem_u32(sm);
    auto Aoff = [](int st, int r, int c) -> uint32_t {
        return (uint32_t)st * BG_AS_STG + ((uint32_t)r * 40u + (uint32_t)c) * 2u;
    };
    auto Boff = [](int st, int r, int c) -> uint32_t {
        return BG_BS_OFF + (uint32_t)st * BG_BS_STG +
               ((uint32_t)r * 136u + (uint32_t)c) * 2u;
    };

    const int b  = blockIdx.z;
    const int m0 = blockIdx.y * 256;
    const int n0 = blockIdx.x * 128;

    A += (long)b * sA;
    B += (long)b * sB;

    const int tid  = threadIdx.x;
    const int wid  = tid >> 5;
    const int lane = tid & 31;
    const int wm   = (wid >> 1) * 64;   // 4 warps in M
    const int wn   = (wid & 1) * 64;    // 2 warps in N

    float acc[4][8][4];
    #pragma unroll
    for (int i = 0; i < 4; i++)
        #pragma unroll
        for (int j = 0; j < 8; j++)
            #pragma unroll
            for (int r = 0; r < 4; r++) acc[i][j][r] = 0.f;

    auto load_stage = [&](int st, int k0) {
        #pragma unroll
        for (int p = 0; p < 4; p++) {
            int seg = tid * 4 + p;           // 0..1023
            int r = seg >> 2, sc = seg & 3;
            cp16(sbase + Aoff(st, r, sc * 8),
                 A + (long)(m0 + r) * ldA + k0 + sc * 8);
        }
        #pragma unroll
        for (int p = 0; p < 2; p++) {
            int seg = tid * 2 + p;           // 0..511
            int r = seg >> 4, sc = seg & 15;
            cp16(sbase + Boff(st, r, sc * 8),
                 B + (long)(k0 + r) * ldB + n0 + sc * 8);
        }
        asm volatile("cp.async.commit_group;");
    };

    const int KT = K >> 5;
    load_stage(0, 0);

    for (int kt = 0; kt < KT; kt++) {
        const int st = kt & 1;
        if (kt + 1 < KT) {
            load_stage(st ^ 1, (kt + 1) * 32);
            asm volatile("cp.async.wait_group 1;");
        } else {
            asm volatile("cp.async.wait_group 0;");
        }
        __syncthreads();

        #pragma unroll
        for (int kk = 0; kk < 2; kk++) {
            uint32_t af[4][4];
            #pragma unroll
            for (int mi = 0; mi < 4; mi++)
                ldsm_x4(af[mi], sbase + Aoff(st, wm + mi * 16 + (lane & 15),
                                             kk * 16 + ((lane >> 4) & 1) * 8));
            uint32_t bf[8][2];
            #pragma unroll
            for (int ni = 0; ni < 8; ni++)
                ldsm_x2_t(bf[ni], sbase + Boff(st, kk * 16 + (lane & 15),
                                               wn + ni * 8));
            #pragma unroll
            for (int mi = 0; mi < 4; mi++)
                #pragma unroll
                for (int ni = 0; ni < 8; ni++)
                    mma_bf16(acc[mi][ni], af[mi], bf[ni]);
        }
        __syncthreads();
    }

    const int rbase = lane >> 2;
    const int cbase = (lane & 3) * 2;
    if (EPI == 0) {
        __nv_bfloat16* Cb = (__nv_bfloat16*)Cv + (long)b * sC;
        #pragma unroll
        for (int mi = 0; mi < 4; mi++) {
            #pragma unroll
            for (int ni = 0; ni < 8; ni++) {
                int row = m0 + wm + mi * 16 + rbase;
                int col = n0 + wn + ni * 8 + cbase;
                float bv0 = bias[row], bv1 = bias[row + 8];
                *(__nv_bfloat162*)&Cb[(long)row * ldC + col] =
                    __floats2bfloat162_rn(acc[mi][ni][0] + bv0, acc[mi][ni][1] + bv0);
                *(__nv_bfloat162*)&Cb[(long)(row + 8) * ldC + col] =
                    __floats2bfloat162_rn(acc[mi][ni][2] + bv1, acc[mi][ni][3] + bv1);
            }
        }
    } else {
        float* Cf = (float*)Cv + (long)b * sC;
        const float* R = resid + (long)b * sR;
        const float gm = gamma[0];
        #pragma unroll
        for (int mi = 0; mi < 4; mi++) {
            #pragma unroll
            for (int ni = 0; ni < 8; ni++) {
                int row = m0 + wm + mi * 16 + rbase;
                int col = n0 + wn + ni * 8 + cbase;
                float2 r0 = *(const float2*)&R[(long)row * ldC + col];
                float2 r1 = *(const float2*)&R[(long)(row + 8) * ldC + col];
                float2 o0, o1;
                o0.x = gm * acc[mi][ni][0] + r0.x;
                o0.y = gm * acc[mi][ni][1] + r0.y;
                o1.x = gm * acc[mi][ni][2] + r1.x;
                o1.y = gm * acc[mi][ni][3] + r1.y;
                *(float2*)&Cf[(long)row * ldC + col] = o0;
                *(float2*)&Cf[(long)(row + 8) * ldC + col] = o1;
            }
        }
    }
}

// ===========================================================================
// kernel_launch  — inputs: x, Wf, bf, Wg, bg, Wh, bh, gamma
// ===========================================================================
extern "C" void kernel_launch(void* const* d_in, const int* in_sizes, int n_in,
                              void* d_out, int out_size)
{
    const float* x     = (const float*)d_in[0];
    const float* Wf    = (const float*)d_in[1];
    const float* bfp   = (const float*)d_in[2];
    const float* Wg    = (const float*)d_in[3];
    const float* bgp   = (const float*)d_in[4];
    const float* Wh    = (const float*)d_in[5];
    const float* bh    = (const float*)d_in[6];
    const float* gamma = (const float*)d_in[7];
    float* out = (float*)d_out;

    void *pxb, *pwfg, *pwh, *pbfg, *pfg, *pft, *ph, *pab, *psp, *psf;
    cudaGetSymbolAddress(&pxb,  d_xb);
    cudaGetSymbolAddress(&pwfg, d_Wfgb);
    cudaGetSymbolAddress(&pwh,  d_Whb);
    cudaGetSymbolAddress(&pbfg, d_bfg);
    cudaGetSymbolAddress(&pfg,  d_fgb);
    cudaGetSymbolAddress(&pft,  d_fTb);
    cudaGetSymbolAddress(&ph,   d_hvb);
    cudaGetSymbolAddress(&pab,  d_attnb);
    cudaGetSymbolAddress(&psp,  d_statsP);
    cudaGetSymbolAddress(&psf,  d_statsF);
    __nv_bfloat16* xb    = (__nv_bfloat16*)pxb;
    __nv_bfloat16* Wfgb  = (__nv_bfloat16*)pwfg;
    __nv_bfloat16* Whb   = (__nv_bfloat16*)pwh;
    float*         bfg   = (float*)pbfg;
    __nv_bfloat16* fgb   = (__nv_bfloat16*)pfg;
    __nv_bfloat16* fTb   = (__nv_bfloat16*)pft;
    __nv_bfloat16* hvb   = (__nv_bfloat16*)ph;
    __nv_bfloat16* attnb = (__nv_bfloat16*)pab;
    float2*        statsP = (float2*)psp;
    float2*        statsF = (float2*)psf;

    const long sx  = (long)NC * NTOK;
    const long sfg = (long)2 * NC8 * NTOK;
    const long sat = (long)NTOK * NTOK;

    static bool attr_set = false;
    if (!attr_set) {
        cudaFuncSetAttribute(logits_pass<1>,
                             cudaFuncAttributeMaxDynamicSharedMemorySize, LS_SMEM_TOT);
        cudaFuncSetAttribute(logits_pass<2>,
                             cudaFuncAttributeMaxDynamicSharedMemorySize, LS_SMEM_TOT);
        cudaFuncSetAttribute(gemm_mma_big<0>,
                             cudaFuncAttributeMaxDynamicSharedMemorySize, BG_SMEM_TOT);
        cudaFuncSetAttribute(gemm_mma_big<2>,
                             cudaFuncAttributeMaxDynamicSharedMemorySize, BG_SMEM_TOT);
        attr_set = true;
    }

    // 0) conversions + bias pack
    {
        long n4 = (long)BATCH * NC * NTOK / 4;
        f32_to_bf16<<<(unsigned)((n4 + 255) / 256), 256>>>(x, xb, n4);
        long wfg4 = (long)NC8 * NC / 4;
        f32_to_bf16<<<(unsigned)((wfg4 + 255) / 256), 256>>>(Wf, Wfgb, wfg4);
        f32_to_bf16<<<(unsigned)((wfg4 + 255) / 256), 256>>>(Wg, Wfgb + (long)NC8 * NC, wfg4);
        long wh4 = (long)NC * NC / 4;
        f32_to_bf16<<<(unsigned)((wh4 + 255) / 256), 256>>>(Wh, Whb, wh4);
        pack_bias<<<1, 128>>>(bfp, bgp, bfg);
    }

    // 1) fg = Wfgb @ xb + bfg  (rows 0-63 = f, 64-127 = g)
    gemm_mma_fg<<<dim3(NTOK / 128, 1, BATCH), 256>>>(
        Wfgb, NC, xb, sx, NTOK, fgb, sfg, NTOK, bfg, NC);

    // 1b) hv = Whb @ xb + bh  (256x128 tiles)
    gemm_mma_big<0><<<dim3(NTOK / 128, NC / 256, BATCH), 256, BG_SMEM_TOT>>>(
        Whb, 0, NC, xb, sx, NTOK, hvb, sx, NTOK, bh, nullptr, 0, nullptr, NC);

    // 2) fT = transpose(f)
    transpose_f<<<dim3(NTOK / 64, 1, BATCH), 256>>>(fgb, sfg, fTb);

    // 3) flash-split softmax: pass1 -> combine -> pass2
    logits_pass<1><<<dim3(NTOK / 128, 4, BATCH), 256, LS_SMEM_TOT>>>(
        fTb, fgb + (long)NC8 * NTOK, sfg, statsP, nullptr, nullptr);
    stats_combine<<<(BATCH * NTOK) / 256, 256>>>(statsP, statsF);
    logits_pass<2><<<dim3(NTOK / 128, 4, BATCH), 256, LS_SMEM_TOT>>>(
        fTb, fgb + (long)NC8 * NTOK, sfg, nullptr, statsF, attnb);

    // 4) out = gamma * (hvb @ attn) + x  (256x128 tiles)
    gemm_mma_big<2><<<dim3(NTOK / 128, NC / 256, BATCH), 256, BG_SMEM_TOT>>>(
        hvb, sx, NTOK, attnb, sat, NTOK, out, sx, NTOK,
        nullptr, x, sx, gamma, NTOK);
}

// round 10
// speedup vs baseline: 1.1920x; 1.1920x over previous
#include <cuda_runtime.h>
#include <cuda_fp16.h>
#include <cstdint>

// ---------------------------------------------------------------------------
// B=4, C=512, C8=64, N=4096 — all GEMMs on HMMA (mma.sync f16, fp32 accum)
// R7 structure (best measured: 503us) with fp16 storage everywhere:
// 0) convert: xh=f16(x), Wfgh=f16([Wf;Wg]), Whh=f16(Wh), bias pack
// 1) fg = Wfgh@xh + bfg  (HMMA, f16: rows 0-63 = f, 64-127 = g)
//    hv = Whh @xh + bh   (HMMA, f16)
// 2) fT = transpose(f)
// 3) logits = fT @ g     (HMMA, **fp16** out — halves softmax traffic)
// 4) softmax rows (fp16 in, fp32 math, fp16 attn out)
// 5) out = gamma * (hv @ attn) + x   (HMMA, fused epilogue, fp32 out)
// NOTE: tcgen05 unavailable (toolchain targets compute_103 w/o 'a' features).
// ---------------------------------------------------------------------------

#define BATCH 4
#define NC    512
#define NC8   64
#define NTOK  4096

__device__ __half  d_xh    [(long)BATCH * NC  * NTOK];     //  16 MB
__device__ __half  d_Wfgh  [(long)2 * NC8 * NC];           // 128 KB
__device__ __half  d_Whh   [(long)NC * NC];                // 512 KB
__device__ float   d_bfg   [2 * NC8];
__device__ __half  d_fgh   [(long)BATCH * 2 * NC8 * NTOK]; //   8 MB
__device__ __half  d_fTh   [(long)BATCH * NTOK * NC8];     //   4 MB
__device__ __half  d_hvh   [(long)BATCH * NC  * NTOK];     //  16 MB
__device__ __half  d_logits[(long)BATCH * NTOK * NTOK];    // 128 MB (fp16!)
__device__ __half  d_attnh [(long)BATCH * NTOK * NTOK];    // 128 MB

// ===========================================================================
// small helpers
// ===========================================================================
__device__ __forceinline__ uint32_t smem_u32(const void* p) {
    uint32_t a;
    asm("{ .reg .u64 t; cvta.to.shared.u64 t, %1; cvt.u32.u64 %0, t; }"
        : "=r"(a) : "l"(p));
    return a;
}
__device__ __forceinline__ void cp16(uint32_t s, const void* g) {
    asm volatile("cp.async.cg.shared.global [%0], [%1], 16;" :: "r"(s), "l"(g));
}
__device__ __forceinline__ void ldsm_x4(uint32_t* r, uint32_t a) {
    asm volatile("ldmatrix.sync.aligned.m8n8.x4.shared.b16 {%0,%1,%2,%3}, [%4];"
                 : "=r"(r[0]), "=r"(r[1]), "=r"(r[2]), "=r"(r[3]) : "r"(a));
}
__device__ __forceinline__ void ldsm_x2_t(uint32_t* r, uint32_t a) {
    asm volatile("ldmatrix.sync.aligned.m8n8.x2.trans.shared.b16 {%0,%1}, [%2];"
                 : "=r"(r[0]), "=r"(r[1]) : "r"(a));
}
__device__ __forceinline__ void mma_f16(float* d, const uint32_t* a, const uint32_t* b) {
    asm volatile(
        "mma.sync.aligned.m16n8k16.row.col.f32.f16.f16.f32 "
        "{%0,%1,%2,%3}, {%4,%5,%6,%7}, {%8,%9}, {%0,%1,%2,%3};"
        : "+f"(d[0]), "+f"(d[1]), "+f"(d[2]), "+f"(d[3])
        : "r"(a[0]), "r"(a[1]), "r"(a[2]), "r"(a[3]), "r"(b[0]), "r"(b[1]));
}

// ===========================================================================
// fp32 -> fp16 convert (vectorized) + bias pack
// ===========================================================================
__global__ __launch_bounds__(256) void f32_to_f16(
    const float* __restrict__ in, __half* __restrict__ out, long n4)
{
    long i = (long)blockIdx.x * 256 + threadIdx.x;
    if (i >= n4) return;
    float4 v = ((const float4*)in)[i];
    __half2 p[2];
    p[0] = __floats2half2_rn(v.x, v.y);
    p[1] = __floats2half2_rn(v.z, v.w);
    ((uint2*)out)[i] = *(uint2*)p;
}

__global__ __launch_bounds__(128) void pack_bias(
    const float* __restrict__ bf, const float* __restrict__ bg,
    float* __restrict__ bfg)
{
    int t = threadIdx.x;
    bfg[t] = (t < NC8) ? bf[t] : bg[t - NC8];
}

// ===========================================================================
// fp16 64x64-tile transpose: fT[n, o] = f[o, n]
// ===========================================================================
__global__ __launch_bounds__(256) void transpose_f(
    const __half* __restrict__ in, long sIn,
    __half* __restrict__ outp)
{
    __shared__ __half t[64][72];
    const __half* ip = in + (long)blockIdx.z * sIn;
    __half* op = outp + (long)blockIdx.z * NTOK * NC8;
    const int j0 = blockIdx.x * 64;
    const int tid = threadIdx.x;

    #pragma unroll
    for (int pass = 0; pass < 4; pass++) {
        int v = tid + pass * 256;
        int r = v >> 4, c4 = v & 15;
        uint2 d = *(const uint2*)(ip + (long)r * NTOK + j0 + c4 * 4);
        *(uint2*)&t[r][c4 * 4] = d;
    }
    __syncthreads();
    #pragma unroll
    for (int pass = 0; pass < 4; pass++) {
        int v = tid + pass * 256;
        int r = v >> 4, c4 = v & 15;
        __half tmp[4];
        tmp[0] = t[c4 * 4 + 0][r];
        tmp[1] = t[c4 * 4 + 1][r];
        tmp[2] = t[c4 * 4 + 2][r];
        tmp[3] = t[c4 * 4 + 3][r];
        *(uint2*)(op + (long)(j0 + r) * NC8 + c4 * 4) = *(uint2*)tmp;
    }
}

// ===========================================================================
// Row softmax: fp16 logits in, fp32 math, fp16 attn out.
// One 256-thread block per (batch, row); 16 elements/thread in registers.
// ===========================================================================
__global__ __launch_bounds__(256) void softmax_rows(
    const __half* __restrict__ logits, __half* __restrict__ attnh)
{
    const long row = (long)blockIdx.y * NTOK + blockIdx.x;
    const __half* p = logits + row * NTOK;
    __half* q = attnh + row * NTOK;
    const int tid = threadIdx.x;

    // vectorized load: 8 x __half2 per thread (16 values)
    float v[16];
    float mx = -3.4e38f;
    #pragma unroll
    for (int t = 0; t < 8; t++) {
        __half2 h2 = ((const __half2*)p)[t * 256 + tid];
        float2 f2 = __half22float2(h2);
        v[t * 2 + 0] = f2.x;
        v[t * 2 + 1] = f2.y;
        mx = fmaxf(mx, fmaxf(f2.x, f2.y));
    }

    __shared__ float sred[8];
    #pragma unroll
    for (int o = 16; o > 0; o >>= 1)
        mx = fmaxf(mx, __shfl_xor_sync(0xffffffffu, mx, o));
    if ((tid & 31) == 0) sred[tid >> 5] = mx;
    __syncthreads();
    if (tid == 0) {
        float m2 = sred[0];
        #pragma unroll
        for (int i = 1; i < 8; i++) m2 = fmaxf(m2, sred[i]);
        sred[0] = m2;
    }
    __syncthreads();
    const float rmax = sred[0];
    __syncthreads();

    float s = 0.f;
    #pragma unroll
    for (int t = 0; t < 16; t++) {
        v[t] = __expf(v[t] - rmax);
        s += v[t];
    }
    #pragma unroll
    for (int o = 16; o > 0; o >>= 1)
        s += __shfl_xor_sync(0xffffffffu, s, o);
    if ((tid & 31) == 0) sred[tid >> 5] = s;
    __syncthreads();
    if (tid == 0) {
        float s2 = 0.f;
        #pragma unroll
        for (int i = 0; i < 8; i++) s2 += sred[i];
        sred[0] = s2;
    }
    __syncthreads();
    const float inv = 1.0f / sred[0];

    #pragma unroll
    for (int t = 0; t < 8; t++)
        ((__half2*)q)[t * 256 + tid] =
            __floats2half2_rn(v[t * 2] * inv, v[t * 2 + 1] * inv);
}

// ===========================================================================
// fp16 HMMA GEMM (mma.sync.m16n8k16), 128x128x32 tiles, 256 threads.
//   C[m,n] = sum_k A[m,k] * B[k,n]
//   A row-major (M x K), B row-major (K x N). ldmatrix.trans handles B.
// EPI=0: C(f16) = acc + bias[m]
// EPI=1: C(f16) = acc                      (logits)
// EPI=2: C(f32) = gamma[0]*acc + resid[m,n]
// ===========================================================================

#define APAD 8
#define BPAD 8
#define ALD  (32 + APAD)
#define BLD  (128 + BPAD)

template<int EPI>
__global__ __launch_bounds__(256) void gemm_mma(
    const __half* __restrict__ A, long sA, int ldA,
    const __half* __restrict__ B, long sB, int ldB,
    void*         __restrict__ Cv, long sC, int ldC,
    const float* __restrict__ bias,
    const float* __restrict__ resid, long sR,
    const float* __restrict__ gamma,
    int K)
{
    __shared__ __half As[2][128][ALD];
    __shared__ __half Bs[2][32][BLD];

    const int b  = blockIdx.z;
    const int m0 = blockIdx.y * 128;
    const int n0 = blockIdx.x * 128;

    A += (long)b * sA;
    B += (long)b * sB;

    const int tid  = threadIdx.x;
    const int wid  = tid >> 5;
    const int lane = tid & 31;
    const int wm   = (wid >> 2) * 64;
    const int wn   = (wid & 3) * 32;

    float acc[4][4][4];
    #pragma unroll
    for (int i = 0; i < 4; i++)
        #pragma unroll
        for (int j = 0; j < 4; j++)
            #pragma unroll
            for (int r = 0; r < 4; r++) acc[i][j][r] = 0.f;

    const int aseg0 = tid * 2;
    const int bseg0 = tid * 2;

    auto load_stage = [&](int st, int k0) {
        #pragma unroll
        for (int p = 0; p < 2; p++) {
            int seg = aseg0 + p;
            int r = seg >> 2, sc = seg & 3;
            cp16(smem_u32(&As[st][r][sc * 8]),
                 A + (long)(m0 + r) * ldA + k0 + sc * 8);
        }
        #pragma unroll
        for (int p = 0; p < 2; p++) {
            int seg = bseg0 + p;
            int r = seg >> 4, sc = seg & 15;
            cp16(smem_u32(&Bs[st][r][sc * 8]),
                 B + (long)(k0 + r) * ldB + n0 + sc * 8);
        }
        asm volatile("cp.async.commit_group;");
    };

    const int KT = K >> 5;
    load_stage(0, 0);

    for (int kt = 0; kt < KT; kt++) {
        const int st = kt & 1;
        if (kt + 1 < KT) {
            load_stage(st ^ 1, (kt + 1) * 32);
            asm volatile("cp.async.wait_group 1;");
        } else {
            asm volatile("cp.async.wait_group 0;");
        }
        __syncthreads();

        #pragma unroll
        for (int kk = 0; kk < 2; kk++) {
            uint32_t af[4][4];
            #pragma unroll
            for (int mi = 0; mi < 4; mi++)
                ldsm_x4(af[mi], smem_u32(
                    &As[st][wm + mi * 16 + (lane & 15)][kk * 16 + ((lane >> 4) & 1) * 8]));
            uint32_t bf[4][2];
            #pragma unroll
            for (int ni = 0; ni < 4; ni++)
                ldsm_x2_t(bf[ni], smem_u32(
                    &Bs[st][kk * 16 + (lane & 15)][wn + ni * 8]));
            #pragma unroll
            for (int mi = 0; mi < 4; mi++)
                #pragma unroll
                for (int ni = 0; ni < 4; ni++)
                    mma_f16(acc[mi][ni], af[mi], bf[ni]);
        }
        __syncthreads();
    }

    // ---- epilogue ----
    const int rbase = lane >> 2;
    const int cbase = (lane & 3) * 2;
    if (EPI == 0) {
        __half* Ch = (__half*)Cv + (long)b * sC;
        #pragma unroll
        for (int mi = 0; mi < 4; mi++) {
            #pragma unroll
            for (int ni = 0; ni < 4; ni++) {
                int row = m0 + wm + mi * 16 + rbase;
                int col = n0 + wn + ni * 8 + cbase;
                float bv0 = bias[row], bv1 = bias[row + 8];
                *(__half2*)&Ch[(long)row * ldC + col] =
                    __floats2half2_rn(acc[mi][ni][0] + bv0, acc[mi][ni][1] + bv0);
                *(__half2*)&Ch[(long)(row + 8) * ldC + col] =
                    __floats2half2_rn(acc[mi][ni][2] + bv1, acc[mi][ni][3] + bv1);
            }
        }
    } else if (EPI == 1) {
        __half* Ch = (__half*)Cv + (long)b * sC;
        #pragma unroll
        for (int mi = 0; mi < 4; mi++) {
            #pragma unroll
            for (int ni = 0; ni < 4; ni++) {
                int row = m0 + wm + mi * 16 + rbase;
                int col = n0 + wn + ni * 8 + cbase;
                *(__half2*)&Ch[(long)row * ldC + col] =
                    __floats2half2_rn(acc[mi][ni][0], acc[mi][ni][1]);
                *(__half2*)&Ch[(long)(row + 8) * ldC + col] =
                    __floats2half2_rn(acc[mi][ni][2], acc[mi][ni][3]);
            }
        }
    } else {
        float* Cf = (float*)Cv + (long)b * sC;
        const float* R = resid + (long)b * sR;
        const float gm = gamma[0];
        #pragma unroll
        for (int mi = 0; mi < 4; mi++) {
            #pragma unroll
            for (int ni = 0; ni < 4; ni++) {
                int row = m0 + wm + mi * 16 + rbase;
                int col = n0 + wn + ni * 8 + cbase;
                float2 r0 = *(const float2*)&R[(long)row * ldC + col];
                float2 r1 = *(const float2*)&R[(long)(row + 8) * ldC + col];
                float2 o0, o1;
                o0.x = gm * acc[mi][ni][0] + r0.x;
                o0.y = gm * acc[mi][ni][1] + r0.y;
                o1.x = gm * acc[mi][ni][2] + r1.x;
                o1.y = gm * acc[mi][ni][3] + r1.y;
                *(float2*)&Cf[(long)row * ldC + col] = o0;
                *(float2*)&Cf[(long)(row + 8) * ldC + col] = o1;
            }
        }
    }
}

// ===========================================================================
// kernel_launch  — inputs: x, Wf, bf, Wg, bg, Wh, bh, gamma
// ===========================================================================
extern "C" void kernel_launch(void* const* d_in, const int* in_sizes, int n_in,
                              void* d_out, int out_size)
{
    const float* x     = (const float*)d_in[0];
    const float* Wf    = (const float*)d_in[1];
    const float* bfp   = (const float*)d_in[2];
    const float* Wg    = (const float*)d_in[3];
    const float* bgp   = (const float*)d_in[4];
    const float* Wh    = (const float*)d_in[5];
    const float* bh    = (const float*)d_in[6];
    const float* gamma = (const float*)d_in[7];
    float* out = (float*)d_out;

    void *pxh, *pwfg, *pwh, *pbfg, *pfg, *pft, *ph, *pl, *pah;
    cudaGetSymbolAddress(&pxh,  d_xh);
    cudaGetSymbolAddress(&pwfg, d_Wfgh);
    cudaGetSymbolAddress(&pwh,  d_Whh);
    cudaGetSymbolAddress(&pbfg, d_bfg);
    cudaGetSymbolAddress(&pfg,  d_fgh);
    cudaGetSymbolAddress(&pft,  d_fTh);
    cudaGetSymbolAddress(&ph,   d_hvh);
    cudaGetSymbolAddress(&pl,   d_logits);
    cudaGetSymbolAddress(&pah,  d_attnh);
    __half* xh     = (__half*)pxh;
    __half* Wfgh   = (__half*)pwfg;
    __half* Whh    = (__half*)pwh;
    float*  bfg    = (float*)pbfg;
    __half* fgh    = (__half*)pfg;
    __half* fTh    = (__half*)pft;
    __half* hvh    = (__half*)ph;
    __half* logits = (__half*)pl;
    __half* attnh  = (__half*)pah;

    const long sx  = (long)NC * NTOK;         // x / hv / out batch stride
    const long sfg = (long)2 * NC8 * NTOK;    // fg batch stride
    const long sft = (long)NTOK * NC8;        // fT batch stride
    const long sat = (long)NTOK * NTOK;       // logits/attn batch stride

    // 0) conversions + bias pack
    {
        long n4 = (long)BATCH * NC * NTOK / 4;
        f32_to_f16<<<(unsigned)((n4 + 255) / 256), 256>>>(x, xh, n4);
        long wfg4 = (long)NC8 * NC / 4;
        f32_to_f16<<<(unsigned)((wfg4 + 255) / 256), 256>>>(Wf, Wfgh, wfg4);
        f32_to_f16<<<(unsigned)((wfg4 + 255) / 256), 256>>>(Wg, Wfgh + (long)NC8 * NC, wfg4);
        long wh4 = (long)NC * NC / 4;
        f32_to_f16<<<(unsigned)((wh4 + 255) / 256), 256>>>(Wh, Whh, wh4);
        pack_bias<<<1, 128>>>(bfp, bgp, bfg);
    }

    // 1) fg = Wfgh @ xh + bfg  (rows 0-63 = f, 64-127 = g)
    gemm_mma<0><<<dim3(NTOK / 128, 1, BATCH), 256>>>(
        Wfgh, 0, NC, xh, sx, NTOK, fgh, sfg, NTOK, bfg, nullptr, 0, nullptr, NC);

    // 1b) hv = Whh @ xh + bh
    gemm_mma<0><<<dim3(NTOK / 128, NC / 128, BATCH), 256>>>(
        Whh, 0, NC, xh, sx, NTOK, hvh, sx, NTOK, bh, nullptr, 0, nullptr, NC);

    // 2) fT = transpose(f)
    transpose_f<<<dim3(NTOK / 64, 1, BATCH), 256>>>(fgh, sfg, fTh);

    // 3) logits = fT @ g  (fp16 out)
    gemm_mma<1><<<dim3(NTOK / 128, NTOK / 128, BATCH), 256>>>(
        fTh, sft, NC8, fgh + (long)NC8 * NTOK, sfg, NTOK,
        logits, sat, NTOK, nullptr, nullptr, 0, nullptr, NC8);

    // 4) softmax (fp16 -> fp16, fp32 math)
    softmax_rows<<<dim3(NTOK, BATCH), 256>>>(logits, attnh);

    // 5) out = gamma * (hvh @ attn) + x
    gemm_mma<2><<<dim3(NTOK / 128, NC / 128, BATCH), 256>>>(
        hvh, sx, NTOK, attnh, sat, NTOK, out, sx, NTOK,
        nullptr, x, sx, gamma, NTOK);
}

// round 11
// speedup vs baseline: 1.3168x; 1.1047x over previous
#include <cuda_runtime.h>
#include <cuda_fp16.h>
#include <cstdint>

// ---------------------------------------------------------------------------
// B=4, C=512, C8=64, N=4096 — all GEMMs on HMMA (mma.sync f16, fp32 accum)
// R10 structure (479.7us) +:
//  - single merged fp32->fp16 convert kernel
//  - 3-stage cp.async pipeline, ONE __syncthreads per k-iter
//  - hv projection forked onto a second stream (overlaps logits/softmax chain)
// Pipeline:
// 0) convert: xh=f16(x), Wfgh=f16([Wf;Wg]), Whh=f16(Wh), bias pack
// 1) fg = Wfgh@xh + bfg  (stream0) ; hv = Whh@xh + bh  (stream2, forked)
// 2) fT = transpose(f)
// 3) logits = fT @ g   (fp16 out)
// 4) softmax rows (fp16 in, fp32 math, fp16 out)
// 5) join; out = gamma * (hv @ attn) + x  (fp32 out)
// NOTE: tcgen05 unavailable (toolchain targets compute_103 w/o 'a' features).
// ---------------------------------------------------------------------------

#define BATCH 4
#define NC    512
#define NC8   64
#define NTOK  4096

__device__ __half  d_xh    [(long)BATCH * NC  * NTOK];     //  16 MB
__device__ __half  d_Wfgh  [(long)2 * NC8 * NC];           // 128 KB
__device__ __half  d_Whh   [(long)NC * NC];                // 512 KB
__device__ float   d_bfg   [2 * NC8];
__device__ __half  d_fgh   [(long)BATCH * 2 * NC8 * NTOK]; //   8 MB
__device__ __half  d_fTh   [(long)BATCH * NTOK * NC8];     //   4 MB
__device__ __half  d_hvh   [(long)BATCH * NC  * NTOK];     //  16 MB
__device__ __half  d_logits[(long)BATCH * NTOK * NTOK];    // 128 MB
__device__ __half  d_attnh [(long)BATCH * NTOK * NTOK];    // 128 MB

// ===========================================================================
// small helpers
// ===========================================================================
__device__ __forceinline__ uint32_t smem_u32(const void* p) {
    uint32_t a;
    asm("{ .reg .u64 t; cvta.to.shared.u64 t, %1; cvt.u32.u64 %0, t; }"
        : "=r"(a) : "l"(p));
    return a;
}
__device__ __forceinline__ void cp16(uint32_t s, const void* g) {
    asm volatile("cp.async.cg.shared.global [%0], [%1], 16;" :: "r"(s), "l"(g));
}
__device__ __forceinline__ void ldsm_x4(uint32_t* r, uint32_t a) {
    asm volatile("ldmatrix.sync.aligned.m8n8.x4.shared.b16 {%0,%1,%2,%3}, [%4];"
                 : "=r"(r[0]), "=r"(r[1]), "=r"(r[2]), "=r"(r[3]) : "r"(a));
}
__device__ __forceinline__ void ldsm_x2_t(uint32_t* r, uint32_t a) {
    asm volatile("ldmatrix.sync.aligned.m8n8.x2.trans.shared.b16 {%0,%1}, [%2];"
                 : "=r"(r[0]), "=r"(r[1]) : "r"(a));
}
__device__ __forceinline__ void mma_f16(float* d, const uint32_t* a, const uint32_t* b) {
    asm volatile(
        "mma.sync.aligned.m16n8k16.row.col.f32.f16.f16.f32 "
        "{%0,%1,%2,%3}, {%4,%5,%6,%7}, {%8,%9}, {%0,%1,%2,%3};"
        : "+f"(d[0]), "+f"(d[1]), "+f"(d[2]), "+f"(d[3])
        : "r"(a[0]), "r"(a[1]), "r"(a[2]), "r"(a[3]), "r"(b[0]), "r"(b[1]));
}

// ===========================================================================
// merged fp32 -> fp16 convert (x, Wf, Wg, Wh in one launch)
// ===========================================================================
#define X4SEG  ((long)BATCH * NC * NTOK / 4)   // 2,097,152
#define WF4SEG ((long)NC8 * NC / 4)            // 8,192
#define WH4SEG ((long)NC * NC / 4)             // 65,536
#define CVT_TOTAL (X4SEG + 2 * WF4SEG + WH4SEG)

__global__ __launch_bounds__(256) void convert_all(
    const float* __restrict__ x,  const float* __restrict__ Wf,
    const float* __restrict__ Wg, const float* __restrict__ Wh,
    __half* __restrict__ xh, __half* __restrict__ Wfgh, __half* __restrict__ Whh)
{
    long i = (long)blockIdx.x * 256 + threadIdx.x;
    if (i >= CVT_TOTAL) return;
    const float* src;
    __half* dst;
    long j;
    if (i < X4SEG)                  { src = x;  dst = xh;   j = i; }
    else if (i < X4SEG + WF4SEG)    { src = Wf; dst = Wfgh; j = i - X4SEG; }
    else if (i < X4SEG + 2*WF4SEG)  { src = Wg; dst = Wfgh + (long)NC8 * NC;
                                      j = i - X4SEG - WF4SEG; }
    else                            { src = Wh; dst = Whh;  j = i - X4SEG - 2*WF4SEG; }
    float4 v = ((const float4*)src)[j];
    __half2 p[2];
    p[0] = __floats2half2_rn(v.x, v.y);
    p[1] = __floats2half2_rn(v.z, v.w);
    ((uint2*)dst)[j] = *(uint2*)p;
}

__global__ __launch_bounds__(128) void pack_bias(
    const float* __restrict__ bf, const float* __restrict__ bg,
    float* __restrict__ bfg)
{
    int t = threadIdx.x;
    bfg[t] = (t < NC8) ? bf[t] : bg[t - NC8];
}

// ===========================================================================
// fp16 64x64-tile transpose: fT[n, o] = f[o, n]
// ===========================================================================
__global__ __launch_bounds__(256) void transpose_f(
    const __half* __restrict__ in, long sIn,
    __half* __restrict__ outp)
{
    __shared__ __half t[64][72];
    const __half* ip = in + (long)blockIdx.z * sIn;
    __half* op = outp + (long)blockIdx.z * NTOK * NC8;
    const int j0 = blockIdx.x * 64;
    const int tid = threadIdx.x;

    #pragma unroll
    for (int pass = 0; pass < 4; pass++) {
        int v = tid + pass * 256;
        int r = v >> 4, c4 = v & 15;
        uint2 d = *(const uint2*)(ip + (long)r * NTOK + j0 + c4 * 4);
        *(uint2*)&t[r][c4 * 4] = d;
    }
    __syncthreads();
    #pragma unroll
    for (int pass = 0; pass < 4; pass++) {
        int v = tid + pass * 256;
        int r = v >> 4, c4 = v & 15;
        __half tmp[4];
        tmp[0] = t[c4 * 4 + 0][r];
        tmp[1] = t[c4 * 4 + 1][r];
        tmp[2] = t[c4 * 4 + 2][r];
        tmp[3] = t[c4 * 4 + 3][r];
        *(uint2*)(op + (long)(j0 + r) * NC8 + c4 * 4) = *(uint2*)tmp;
    }
}

// ===========================================================================
// Row softmax: fp16 logits in, fp32 math, fp16 attn out.
// ===========================================================================
__global__ __launch_bounds__(256) void softmax_rows(
    const __half* __restrict__ logits, __half* __restrict__ attnh)
{
    const long row = (long)blockIdx.y * NTOK + blockIdx.x;
    const __half* p = logits + row * NTOK;
    __half* q = attnh + row * NTOK;
    const int tid = threadIdx.x;

    float v[16];
    float mx = -3.4e38f;
    #pragma unroll
    for (int t = 0; t < 8; t++) {
        __half2 h2 = ((const __half2*)p)[t * 256 + tid];
        float2 f2 = __half22float2(h2);
        v[t * 2 + 0] = f2.x;
        v[t * 2 + 1] = f2.y;
        mx = fmaxf(mx, fmaxf(f2.x, f2.y));
    }

    __shared__ float sred[8];
    #pragma unroll
    for (int o = 16; o > 0; o >>= 1)
        mx = fmaxf(mx, __shfl_xor_sync(0xffffffffu, mx, o));
    if ((tid & 31) == 0) sred[tid >> 5] = mx;
    __syncthreads();
    if (tid == 0) {
        float m2 = sred[0];
        #pragma unroll
        for (int i = 1; i < 8; i++) m2 = fmaxf(m2, sred[i]);
        sred[0] = m2;
    }
    __syncthreads();
    const float rmax = sred[0];
    __syncthreads();

    float s = 0.f;
    #pragma unroll
    for (int t = 0; t < 16; t++) {
        v[t] = __expf(v[t] - rmax);
        s += v[t];
    }
    #pragma unroll
    for (int o = 16; o > 0; o >>= 1)
        s += __shfl_xor_sync(0xffffffffu, s, o);
    if ((tid & 31) == 0) sred[tid >> 5] = s;
    __syncthreads();
    if (tid == 0) {
        float s2 = 0.f;
        #pragma unroll
        for (int i = 0; i < 8; i++) s2 += sred[i];
        sred[0] = s2;
    }
    __syncthreads();
    const float inv = 1.0f / sred[0];

    #pragma unroll
    for (int t = 0; t < 8; t++)
        ((__half2*)q)[t * 256 + tid] =
            __floats2half2_rn(v[t * 2] * inv, v[t * 2 + 1] * inv);
}

// ===========================================================================
// fp16 HMMA GEMM (mma.sync.m16n8k16), 128x128x32 tiles, 256 threads,
// 3-stage cp.async pipeline, one __syncthreads per k-iter.
// EPI=0: C(f16) = acc + bias[m]
// EPI=1: C(f16) = acc
// EPI=2: C(f32) = gamma[0]*acc + resid[m,n]
// Dynamic smem: 3*(128*40 + 32*136)*2 = 56832 B
// ===========================================================================

#define G_ALD 40u
#define G_BLD 136u
#define G_ASZ (128u * G_ALD * 2u)          // 10240
#define G_BSZ (32u * G_BLD * 2u)           // 8704
#define G_BBASE (3u * G_ASZ)               // 30720
#define G_SMEM (G_BBASE + 3u * G_BSZ)      // 56832

template<int EPI>
__global__ __launch_bounds__(256, 2) void gemm_mma(
    const __half* __restrict__ A, long sA, int ldA,
    const __half* __restrict__ B, long sB, int ldB,
    void*         __restrict__ Cv, long sC, int ldC,
    const float* __restrict__ bias,
    const float* __restrict__ resid, long sR,
    const float* __restrict__ gamma,
    int K)
{
    extern __shared__ char sm[];
    const uint32_t sb = smem_u32(sm);

    const int b  = blockIdx.z;
    const int m0 = blockIdx.y * 128;
    const int n0 = blockIdx.x * 128;

    A += (long)b * sA;
    B += (long)b * sB;

    const int tid  = threadIdx.x;
    const int wid  = tid >> 5;
    const int lane = tid & 31;
    const int wm   = (wid >> 2) * 64;
    const int wn   = (wid & 3) * 32;

    float acc[4][4][4];
    #pragma unroll
    for (int i = 0; i < 4; i++)
        #pragma unroll
        for (int j = 0; j < 4; j++)
            #pragma unroll
            for (int r = 0; r < 4; r++) acc[i][j][r] = 0.f;

    auto Aaddr = [&](int st, int r, int c) -> uint32_t {
        return sb + (uint32_t)st * G_ASZ + ((uint32_t)r * G_ALD + (uint32_t)c) * 2u;
    };
    auto Baddr = [&](int st, int r, int c) -> uint32_t {
        return sb + G_BBASE + (uint32_t)st * G_BSZ +
               ((uint32_t)r * G_BLD + (uint32_t)c) * 2u;
    };

    auto load_stage = [&](int st, int kt) {
        const int k0 = kt * 32;
        #pragma unroll
        for (int p = 0; p < 2; p++) {
            int seg = tid * 2 + p;
            int r = seg >> 2, sc = seg & 3;
            cp16(Aaddr(st, r, sc * 8), A + (long)(m0 + r) * ldA + k0 + sc * 8);
        }
        #pragma unroll
        for (int p = 0; p < 2; p++) {
            int seg = tid * 2 + p;
            int r = seg >> 4, sc = seg & 15;
            cp16(Baddr(st, r, sc * 8), B + (long)(k0 + r) * ldB + n0 + sc * 8);
        }
        asm volatile("cp.async.commit_group;");
    };

    const int KT = K >> 5;   // K/32, always >= 2 here
    load_stage(0, 0);
    load_stage(1, 1);

    int st = 0;
    for (int kt = 0; kt < KT; kt++) {
        if (kt + 1 < KT) asm volatile("cp.async.wait_group 1;");
        else             asm volatile("cp.async.wait_group 0;");
        __syncthreads();

        if (kt + 2 < KT) {
            int st2 = st + 2; if (st2 >= 3) st2 -= 3;
            load_stage(st2, kt + 2);
        }

        #pragma unroll
        for (int kk = 0; kk < 2; kk++) {
            uint32_t af[4][4];
            #pragma unroll
            for (int mi = 0; mi < 4; mi++)
                ldsm_x4(af[mi], Aaddr(st, wm + mi * 16 + (lane & 15),
                                      kk * 16 + ((lane >> 4) & 1) * 8));
            uint32_t bf[4][2];
            #pragma unroll
            for (int ni = 0; ni < 4; ni++)
                ldsm_x2_t(bf[ni], Baddr(st, kk * 16 + (lane & 15), wn + ni * 8));
            #pragma unroll
            for (int mi = 0; mi < 4; mi++)
                #pragma unroll
                for (int ni = 0; ni < 4; ni++)
                    mma_f16(acc[mi][ni], af[mi], bf[ni]);
        }
        if (++st == 3) st = 0;
    }

    // ---- epilogue ----
    const int rbase = lane >> 2;
    const int cbase = (lane & 3) * 2;
    if (EPI == 0) {
        __half* Ch = (__half*)Cv + (long)b * sC;
        #pragma unroll
        for (int mi = 0; mi < 4; mi++) {
            #pragma unroll
            for (int ni = 0; ni < 4; ni++) {
                int row = m0 + wm + mi * 16 + rbase;
                int col = n0 + wn + ni * 8 + cbase;
                float bv0 = bias[row], bv1 = bias[row + 8];
                *(__half2*)&Ch[(long)row * ldC + col] =
                    __floats2half2_rn(acc[mi][ni][0] + bv0, acc[mi][ni][1] + bv0);
                *(__half2*)&Ch[(long)(row + 8) * ldC + col] =
                    __floats2half2_rn(acc[mi][ni][2] + bv1, acc[mi][ni][3] + bv1);
            }
        }
    } else if (EPI == 1) {
        __half* Ch = (__half*)Cv + (long)b * sC;
        #pragma unroll
        for (int mi = 0; mi < 4; mi++) {
            #pragma unroll
            for (int ni = 0; ni < 4; ni++) {
                int row = m0 + wm + mi * 16 + rbase;
                int col = n0 + wn + ni * 8 + cbase;
                *(__half2*)&Ch[(long)row * ldC + col] =
                    __floats2half2_rn(acc[mi][ni][0], acc[mi][ni][1]);
                *(__half2*)&Ch[(long)(row + 8) * ldC + col] =
                    __floats2half2_rn(acc[mi][ni][2], acc[mi][ni][3]);
            }
        }
    } else {
        float* Cf = (float*)Cv + (long)b * sC;
        const float* R = resid + (long)b * sR;
        const float gm = gamma[0];
        #pragma unroll
        for (int mi = 0; mi < 4; mi++) {
            #pragma unroll
            for (int ni = 0; ni < 4; ni++) {
                int row = m0 + wm + mi * 16 + rbase;
                int col = n0 + wn + ni * 8 + cbase;
                float2 r0 = *(const float2*)&R[(long)row * ldC + col];
                float2 r1 = *(const float2*)&R[(long)(row + 8) * ldC + col];
                float2 o0, o1;
                o0.x = gm * acc[mi][ni][0] + r0.x;
                o0.y = gm * acc[mi][ni][1] + r0.y;
                o1.x = gm * acc[mi][ni][2] + r1.x;
                o1.y = gm * acc[mi][ni][3] + r1.y;
                *(float2*)&Cf[(long)row * ldC + col] = o0;
                *(float2*)&Cf[(long)(row + 8) * ldC + col] = o1;
            }
        }
    }
}

// ===========================================================================
// kernel_launch  — inputs: x, Wf, bf, Wg, bg, Wh, bh, gamma
// ===========================================================================
extern "C" void kernel_launch(void* const* d_in, const int* in_sizes, int n_in,
                              void* d_out, int out_size)
{
    const float* x     = (const float*)d_in[0];
    const float* Wf    = (const float*)d_in[1];
    const float* bfp   = (const float*)d_in[2];
    const float* Wg    = (const float*)d_in[3];
    const float* bgp   = (const float*)d_in[4];
    const float* Wh    = (const float*)d_in[5];
    const float* bh    = (const float*)d_in[6];
    const float* gamma = (const float*)d_in[7];
    float* out = (float*)d_out;

    void *pxh, *pwfg, *pwh, *pbfg, *pfg, *pft, *ph, *pl, *pah;
    cudaGetSymbolAddress(&pxh,  d_xh);
    cudaGetSymbolAddress(&pwfg, d_Wfgh);
    cudaGetSymbolAddress(&pwh,  d_Whh);
    cudaGetSymbolAddress(&pbfg, d_bfg);
    cudaGetSymbolAddress(&pfg,  d_fgh);
    cudaGetSymbolAddress(&pft,  d_fTh);
    cudaGetSymbolAddress(&ph,   d_hvh);
    cudaGetSymbolAddress(&pl,   d_logits);
    cudaGetSymbolAddress(&pah,  d_attnh);
    __half* xh     = (__half*)pxh;
    __half* Wfgh   = (__half*)pwfg;
    __half* Whh    = (__half*)pwh;
    float*  bfg    = (float*)pbfg;
    __half* fgh    = (__half*)pfg;
    __half* fTh    = (__half*)pft;
    __half* hvh    = (__half*)ph;
    __half* logits = (__half*)pl;
    __half* attnh  = (__half*)pah;

    const long sx  = (long)NC * NTOK;
    const long sfg = (long)2 * NC8 * NTOK;
    const long sft = (long)NTOK * NC8;
    const long sat = (long)NTOK * NTOK;

    static cudaStream_t s2 = nullptr;
    static cudaEvent_t ev_fork = nullptr, ev_join = nullptr;
    static bool init_done = false;
    if (!init_done) {
        cudaFuncSetAttribute(gemm_mma<0>,
                             cudaFuncAttributeMaxDynamicSharedMemorySize, G_SMEM);
        cudaFuncSetAttribute(gemm_mma<1>,
                             cudaFuncAttributeMaxDynamicSharedMemorySize, G_SMEM);
        cudaFuncSetAttribute(gemm_mma<2>,
                             cudaFuncAttributeMaxDynamicSharedMemorySize, G_SMEM);
        cudaStreamCreateWithFlags(&s2, cudaStreamNonBlocking);
        cudaEventCreateWithFlags(&ev_fork, cudaEventDisableTiming);
        cudaEventCreateWithFlags(&ev_join, cudaEventDisableTiming);
        init_done = true;
    }

    // 0) conversions + bias pack (stream 0)
    convert_all<<<(unsigned)((CVT_TOTAL + 255) / 256), 256>>>(
        x, Wf, Wg, Wh, xh, Wfgh, Whh);
    pack_bias<<<1, 128>>>(bfp, bgp, bfg);

    // fork: hv projection runs on s2, overlapping the logits/softmax chain
    cudaEventRecord(ev_fork, 0);
    cudaStreamWaitEvent(s2, ev_fork, 0);

    // 1b) hv = Whh @ xh + bh   (stream s2)
    gemm_mma<0><<<dim3(NTOK / 128, NC / 128, BATCH), 256, G_SMEM, s2>>>(
        Whh, 0, NC, xh, sx, NTOK, hvh, sx, NTOK, bh, nullptr, 0, nullptr, NC);
    cudaEventRecord(ev_join, s2);

    // 1) fg = Wfgh @ xh + bfg  (stream 0; rows 0-63 = f, 64-127 = g)
    gemm_mma<0><<<dim3(NTOK / 128, 1, BATCH), 256, G_SMEM>>>(
        Wfgh, 0, NC, xh, sx, NTOK, fgh, sfg, NTOK, bfg, nullptr, 0, nullptr, NC);

    // 2) fT = transpose(f)
    transpose_f<<<dim3(NTOK / 64, 1, BATCH), 256>>>(fgh, sfg, fTh);

    // 3) logits = fT @ g  (fp16 out)
    gemm_mma<1><<<dim3(NTOK / 128, NTOK / 128, BATCH), 256, G_SMEM>>>(
        fTh, sft, NC8, fgh + (long)NC8 * NTOK, sfg, NTOK,
        logits, sat, NTOK, nullptr, nullptr, 0, nullptr, NC8);

    // 4) softmax (fp16 -> fp16, fp32 math)
    softmax_rows<<<dim3(NTOK, BATCH), 256>>>(logits, attnh);

    // join hv before the final GEMM
    cudaStreamWaitEvent(0, ev_join, 0);

    // 5) out = gamma * (hvh @ attn) + x
    gemm_mma<2><<<dim3(NTOK / 128, NC / 128, BATCH), 256, G_SMEM>>>(
        hvh, sx, NTOK, attnh, sat, NTOK, out, sx, NTOK,
        nullptr, x, sx, gamma, NTOK);
}

// round 12
// speedup vs baseline: 1.3420x; 1.0192x over previous
#include <cuda_runtime.h>
#include <cuda_fp16.h>
#include <cstdint>

// ---------------------------------------------------------------------------
// B=4, C=512, C8=64, N=4096 — all GEMMs on HMMA (mma.sync f16, fp32 accum)
// R11 structure (434.2us) + final GEMM on a 128x256 CTA tile (512 threads,
// 16 warps, same 64x32 warptile / per-thread budget) to cut L2 traffic 25%.
// Pipeline:
// 0) convert: xh=f16(x), Wfgh=f16([Wf;Wg]), Whh=f16(Wh), bias pack
// 1) fg = Wfgh@xh + bfg  (stream0) ; hv = Whh@xh + bh  (stream2, forked)
// 2) fT = transpose(f)
// 3) logits = fT @ g   (fp16 out)
// 4) softmax rows (fp16 in, fp32 math, fp16 out)
// 5) join; out = gamma * (hv @ attn) + x  (wide HMMA, fp32 out)
// NOTE: tcgen05 unavailable (toolchain targets compute_103 w/o 'a' features).
// ---------------------------------------------------------------------------

#define BATCH 4
#define NC    512
#define NC8   64
#define NTOK  4096

__device__ __half  d_xh    [(long)BATCH * NC  * NTOK];     //  16 MB
__device__ __half  d_Wfgh  [(long)2 * NC8 * NC];           // 128 KB
__device__ __half  d_Whh   [(long)NC * NC];                // 512 KB
__device__ float   d_bfg   [2 * NC8];
__device__ __half  d_fgh   [(long)BATCH * 2 * NC8 * NTOK]; //   8 MB
__device__ __half  d_fTh   [(long)BATCH * NTOK * NC8];     //   4 MB
__device__ __half  d_hvh   [(long)BATCH * NC  * NTOK];     //  16 MB
__device__ __half  d_logits[(long)BATCH * NTOK * NTOK];    // 128 MB
__device__ __half  d_attnh [(long)BATCH * NTOK * NTOK];    // 128 MB

// ===========================================================================
// small helpers
// ===========================================================================
__device__ __forceinline__ uint32_t smem_u32(const void* p) {
    uint32_t a;
    asm("{ .reg .u64 t; cvta.to.shared.u64 t, %1; cvt.u32.u64 %0, t; }"
        : "=r"(a) : "l"(p));
    return a;
}
__device__ __forceinline__ void cp16(uint32_t s, const void* g) {
    asm volatile("cp.async.cg.shared.global [%0], [%1], 16;" :: "r"(s), "l"(g));
}
__device__ __forceinline__ void ldsm_x4(uint32_t* r, uint32_t a) {
    asm volatile("ldmatrix.sync.aligned.m8n8.x4.shared.b16 {%0,%1,%2,%3}, [%4];"
                 : "=r"(r[0]), "=r"(r[1]), "=r"(r[2]), "=r"(r[3]) : "r"(a));
}
__device__ __forceinline__ void ldsm_x2_t(uint32_t* r, uint32_t a) {
    asm volatile("ldmatrix.sync.aligned.m8n8.x2.trans.shared.b16 {%0,%1}, [%2];"
                 : "=r"(r[0]), "=r"(r[1]) : "r"(a));
}
__device__ __forceinline__ void mma_f16(float* d, const uint32_t* a, const uint32_t* b) {
    asm volatile(
        "mma.sync.aligned.m16n8k16.row.col.f32.f16.f16.f32 "
        "{%0,%1,%2,%3}, {%4,%5,%6,%7}, {%8,%9}, {%0,%1,%2,%3};"
        : "+f"(d[0]), "+f"(d[1]), "+f"(d[2]), "+f"(d[3])
        : "r"(a[0]), "r"(a[1]), "r"(a[2]), "r"(a[3]), "r"(b[0]), "r"(b[1]));
}

// ===========================================================================
// merged fp32 -> fp16 convert (x, Wf, Wg, Wh in one launch)
// ===========================================================================
#define X4SEG  ((long)BATCH * NC * NTOK / 4)
#define WF4SEG ((long)NC8 * NC / 4)
#define WH4SEG ((long)NC * NC / 4)
#define CVT_TOTAL (X4SEG + 2 * WF4SEG + WH4SEG)

__global__ __launch_bounds__(256) void convert_all(
    const float* __restrict__ x,  const float* __restrict__ Wf,
    const float* __restrict__ Wg, const float* __restrict__ Wh,
    __half* __restrict__ xh, __half* __restrict__ Wfgh, __half* __restrict__ Whh)
{
    long i = (long)blockIdx.x * 256 + threadIdx.x;
    if (i >= CVT_TOTAL) return;
    const float* src;
    __half* dst;
    long j;
    if (i < X4SEG)                  { src = x;  dst = xh;   j = i; }
    else if (i < X4SEG + WF4SEG)    { src = Wf; dst = Wfgh; j = i - X4SEG; }
    else if (i < X4SEG + 2*WF4SEG)  { src = Wg; dst = Wfgh + (long)NC8 * NC;
                                      j = i - X4SEG - WF4SEG; }
    else                            { src = Wh; dst = Whh;  j = i - X4SEG - 2*WF4SEG; }
    float4 v = ((const float4*)src)[j];
    __half2 p[2];
    p[0] = __floats2half2_rn(v.x, v.y);
    p[1] = __floats2half2_rn(v.z, v.w);
    ((uint2*)dst)[j] = *(uint2*)p;
}

__global__ __launch_bounds__(128) void pack_bias(
    const float* __restrict__ bf, const float* __restrict__ bg,
    float* __restrict__ bfg)
{
    int t = threadIdx.x;
    bfg[t] = (t < NC8) ? bf[t] : bg[t - NC8];
}

// ===========================================================================
// fp16 64x64-tile transpose: fT[n, o] = f[o, n]
// ===========================================================================
__global__ __launch_bounds__(256) void transpose_f(
    const __half* __restrict__ in, long sIn,
    __half* __restrict__ outp)
{
    __shared__ __half t[64][72];
    const __half* ip = in + (long)blockIdx.z * sIn;
    __half* op = outp + (long)blockIdx.z * NTOK * NC8;
    const int j0 = blockIdx.x * 64;
    const int tid = threadIdx.x;

    #pragma unroll
    for (int pass = 0; pass < 4; pass++) {
        int v = tid + pass * 256;
        int r = v >> 4, c4 = v & 15;
        uint2 d = *(const uint2*)(ip + (long)r * NTOK + j0 + c4 * 4);
        *(uint2*)&t[r][c4 * 4] = d;
    }
    __syncthreads();
    #pragma unroll
    for (int pass = 0; pass < 4; pass++) {
        int v = tid + pass * 256;
        int r = v >> 4, c4 = v & 15;
        __half tmp[4];
        tmp[0] = t[c4 * 4 + 0][r];
        tmp[1] = t[c4 * 4 + 1][r];
        tmp[2] = t[c4 * 4 + 2][r];
        tmp[3] = t[c4 * 4 + 3][r];
        *(uint2*)(op + (long)(j0 + r) * NC8 + c4 * 4) = *(uint2*)tmp;
    }
}

// ===========================================================================
// Row softmax: fp16 logits in, fp32 math, fp16 attn out.
// ===========================================================================
__global__ __launch_bounds__(256) void softmax_rows(
    const __half* __restrict__ logits, __half* __restrict__ attnh)
{
    const long row = (long)blockIdx.y * NTOK + blockIdx.x;
    const __half* p = logits + row * NTOK;
    __half* q = attnh + row * NTOK;
    const int tid = threadIdx.x;

    float v[16];
    float mx = -3.4e38f;
    #pragma unroll
    for (int t = 0; t < 8; t++) {
        __half2 h2 = ((const __half2*)p)[t * 256 + tid];
        float2 f2 = __half22float2(h2);
        v[t * 2 + 0] = f2.x;
        v[t * 2 + 1] = f2.y;
        mx = fmaxf(mx, fmaxf(f2.x, f2.y));
    }

    __shared__ float sred[8];
    #pragma unroll
    for (int o = 16; o > 0; o >>= 1)
        mx = fmaxf(mx, __shfl_xor_sync(0xffffffffu, mx, o));
    if ((tid & 31) == 0) sred[tid >> 5] = mx;
    __syncthreads();
    if (tid == 0) {
        float m2 = sred[0];
        #pragma unroll
        for (int i = 1; i < 8; i++) m2 = fmaxf(m2, sred[i]);
        sred[0] = m2;
    }
    __syncthreads();
    const float rmax = sred[0];
    __syncthreads();

    float s = 0.f;
    #pragma unroll
    for (int t = 0; t < 16; t++) {
        v[t] = __expf(v[t] - rmax);
        s += v[t];
    }
    #pragma unroll
    for (int o = 16; o > 0; o >>= 1)
        s += __shfl_xor_sync(0xffffffffu, s, o);
    if ((tid & 31) == 0) sred[tid >> 5] = s;
    __syncthreads();
    if (tid == 0) {
        float s2 = 0.f;
        #pragma unroll
        for (int i = 0; i < 8; i++) s2 += sred[i];
        sred[0] = s2;
    }
    __syncthreads();
    const float inv = 1.0f / sred[0];

    #pragma unroll
    for (int t = 0; t < 8; t++)
        ((__half2*)q)[t * 256 + tid] =
            __floats2half2_rn(v[t * 2] * inv, v[t * 2 + 1] * inv);
}

// ===========================================================================
// fp16 HMMA GEMM (mma.sync.m16n8k16), 128x128x32 tiles, 256 threads,
// 3-stage cp.async pipeline, one __syncthreads per k-iter.
// EPI=0: C(f16)=acc+bias[m]; EPI=1: C(f16)=acc
// ===========================================================================

#define G_ALD 40u
#define G_BLD 136u
#define G_ASZ (128u * G_ALD * 2u)
#define G_BSZ (32u * G_BLD * 2u)
#define G_BBASE (3u * G_ASZ)
#define G_SMEM (G_BBASE + 3u * G_BSZ)      // 56832

template<int EPI>
__global__ __launch_bounds__(256, 2) void gemm_mma(
    const __half* __restrict__ A, long sA, int ldA,
    const __half* __restrict__ B, long sB, int ldB,
    void*         __restrict__ Cv, long sC, int ldC,
    const float* __restrict__ bias,
    int K)
{
    extern __shared__ char sm[];
    const uint32_t sb = smem_u32(sm);

    const int b  = blockIdx.z;
    const int m0 = blockIdx.y * 128;
    const int n0 = blockIdx.x * 128;

    A += (long)b * sA;
    B += (long)b * sB;

    const int tid  = threadIdx.x;
    const int wid  = tid >> 5;
    const int lane = tid & 31;
    const int wm   = (wid >> 2) * 64;
    const int wn   = (wid & 3) * 32;

    float acc[4][4][4];
    #pragma unroll
    for (int i = 0; i < 4; i++)
        #pragma unroll
        for (int j = 0; j < 4; j++)
            #pragma unroll
            for (int r = 0; r < 4; r++) acc[i][j][r] = 0.f;

    auto Aaddr = [&](int st, int r, int c) -> uint32_t {
        return sb + (uint32_t)st * G_ASZ + ((uint32_t)r * G_ALD + (uint32_t)c) * 2u;
    };
    auto Baddr = [&](int st, int r, int c) -> uint32_t {
        return sb + G_BBASE + (uint32_t)st * G_BSZ +
               ((uint32_t)r * G_BLD + (uint32_t)c) * 2u;
    };

    auto load_stage = [&](int st, int kt) {
        const int k0 = kt * 32;
        #pragma unroll
        for (int p = 0; p < 2; p++) {
            int seg = tid * 2 + p;
            int r = seg >> 2, sc = seg & 3;
            cp16(Aaddr(st, r, sc * 8), A + (long)(m0 + r) * ldA + k0 + sc * 8);
        }
        #pragma unroll
        for (int p = 0; p < 2; p++) {
            int seg = tid * 2 + p;
            int r = seg >> 4, sc = seg & 15;
            cp16(Baddr(st, r, sc * 8), B + (long)(k0 + r) * ldB + n0 + sc * 8);
        }
        asm volatile("cp.async.commit_group;");
    };

    const int KT = K >> 5;
    load_stage(0, 0);
    load_stage(1, 1);

    int st = 0;
    for (int kt = 0; kt < KT; kt++) {
        if (kt + 1 < KT) asm volatile("cp.async.wait_group 1;");
        else             asm volatile("cp.async.wait_group 0;");
        __syncthreads();

        if (kt + 2 < KT) {
            int st2 = st + 2; if (st2 >= 3) st2 -= 3;
            load_stage(st2, kt + 2);
        }

        #pragma unroll
        for (int kk = 0; kk < 2; kk++) {
            uint32_t af[4][4];
            #pragma unroll
            for (int mi = 0; mi < 4; mi++)
                ldsm_x4(af[mi], Aaddr(st, wm + mi * 16 + (lane & 15),
                                      kk * 16 + ((lane >> 4) & 1) * 8));
            uint32_t bf[4][2];
            #pragma unroll
            for (int ni = 0; ni < 4; ni++)
                ldsm_x2_t(bf[ni], Baddr(st, kk * 16 + (lane & 15), wn + ni * 8));
            #pragma unroll
            for (int mi = 0; mi < 4; mi++)
                #pragma unroll
                for (int ni = 0; ni < 4; ni++)
                    mma_f16(acc[mi][ni], af[mi], bf[ni]);
        }
        if (++st == 3) st = 0;
    }

    const int rbase = lane >> 2;
    const int cbase = (lane & 3) * 2;
    __half* Ch = (__half*)Cv + (long)b * sC;
    #pragma unroll
    for (int mi = 0; mi < 4; mi++) {
        #pragma unroll
        for (int ni = 0; ni < 4; ni++) {
            int row = m0 + wm + mi * 16 + rbase;
            int col = n0 + wn + ni * 8 + cbase;
            float bv0 = (EPI == 0) ? bias[row] : 0.f;
            float bv1 = (EPI == 0) ? bias[row + 8] : 0.f;
            *(__half2*)&Ch[(long)row * ldC + col] =
                __floats2half2_rn(acc[mi][ni][0] + bv0, acc[mi][ni][1] + bv0);
            *(__half2*)&Ch[(long)(row + 8) * ldC + col] =
                __floats2half2_rn(acc[mi][ni][2] + bv1, acc[mi][ni][3] + bv1);
        }
    }
}

// ===========================================================================
// WIDE fp16 HMMA GEMM for the final stage: 128(M) x 256(N) x 32 CTA tile,
// 512 threads / 16 warps, SAME 64x32 warptile and per-thread budget.
// C(f32) = gamma[0]*acc + resid[m,n]
// Dynamic smem: 3*(128*40 + 32*264)*2 = 81408 B
// ===========================================================================

#define W_ALD 40u
#define W_BLD 264u
#define W_ASZ (128u * W_ALD * 2u)          // 10240
#define W_BSZ (32u * W_BLD * 2u)           // 16896
#define W_BBASE (3u * W_ASZ)               // 30720
#define W_SMEM (W_BBASE + 3u * W_BSZ)      // 81408

__global__ __launch_bounds__(512, 1) void gemm_mma_wide(
    const __half* __restrict__ A, long sA, int ldA,
    const __half* __restrict__ B, long sB, int ldB,
    float*        __restrict__ C, long sC, int ldC,
    const float* __restrict__ resid, long sR,
    const float* __restrict__ gamma,
    int K)
{
    extern __shared__ char sm[];
    const uint32_t sb = smem_u32(sm);

    const int b  = blockIdx.z;
    const int m0 = blockIdx.y * 128;
    const int n0 = blockIdx.x * 256;

    A += (long)b * sA;
    B += (long)b * sB;

    const int tid  = threadIdx.x;
    const int wid  = tid >> 5;          // 0..15
    const int lane = tid & 31;
    const int wm   = (wid >> 3) * 64;   // 2 warps in M
    const int wn   = (wid & 7) * 32;    // 8 warps in N

    float acc[4][4][4];
    #pragma unroll
    for (int i = 0; i < 4; i++)
        #pragma unroll
        for (int j = 0; j < 4; j++)
            #pragma unroll
            for (int r = 0; r < 4; r++) acc[i][j][r] = 0.f;

    auto Aaddr = [&](int st, int r, int c) -> uint32_t {
        return sb + (uint32_t)st * W_ASZ + ((uint32_t)r * W_ALD + (uint32_t)c) * 2u;
    };
    auto Baddr = [&](int st, int r, int c) -> uint32_t {
        return sb + W_BBASE + (uint32_t)st * W_BSZ +
               ((uint32_t)r * W_BLD + (uint32_t)c) * 2u;
    };

    auto load_stage = [&](int st, int kt) {
        const int k0 = kt * 32;
        {   // A: 128x32 halves = 512 x 16B segs, 1 per thread
            int r = tid >> 2, sc = tid & 3;
            cp16(Aaddr(st, r, sc * 8), A + (long)(m0 + r) * ldA + k0 + sc * 8);
        }
        #pragma unroll
        for (int p = 0; p < 2; p++) {   // B: 32x256 halves = 1024 segs, 2 per thread
            int seg = tid * 2 + p;
            int r = seg >> 5, sc = seg & 31;
            cp16(Baddr(st, r, sc * 8), B + (long)(k0 + r) * ldB + n0 + sc * 8);
        }
        asm volatile("cp.async.commit_group;");
    };

    const int KT = K >> 5;
    load_stage(0, 0);
    load_stage(1, 1);

    int st = 0;
    for (int kt = 0; kt < KT; kt++) {
        if (kt + 1 < KT) asm volatile("cp.async.wait_group 1;");
        else             asm volatile("cp.async.wait_group 0;");
        __syncthreads();

        if (kt + 2 < KT) {
            int st2 = st + 2; if (st2 >= 3) st2 -= 3;
            load_stage(st2, kt + 2);
        }

        #pragma unroll
        for (int kk = 0; kk < 2; kk++) {
            uint32_t af[4][4];
            #pragma unroll
            for (int mi = 0; mi < 4; mi++)
                ldsm_x4(af[mi], Aaddr(st, wm + mi * 16 + (lane & 15),
                                      kk * 16 + ((lane >> 4) & 1) * 8));
            uint32_t bf[4][2];
            #pragma unroll
            for (int ni = 0; ni < 4; ni++)
                ldsm_x2_t(bf[ni], Baddr(st, kk * 16 + (lane & 15), wn + ni * 8));
            #pragma unroll
            for (int mi = 0; mi < 4; mi++)
                #pragma unroll
                for (int ni = 0; ni < 4; ni++)
                    mma_f16(acc[mi][ni], af[mi], bf[ni]);
        }
        if (++st == 3) st = 0;
    }

    const int rbase = lane >> 2;
    const int cbase = (lane & 3) * 2;
    float* Cf = C + (long)b * sC;
    const float* R = resid + (long)b * sR;
    const float gm = gamma[0];
    #pragma unroll
    for (int mi = 0; mi < 4; mi++) {
        #pragma unroll
        for (int ni = 0; ni < 4; ni++) {
            int row = m0 + wm + mi * 16 + rbase;
            int col = n0 + wn + ni * 8 + cbase;
            float2 r0 = *(const float2*)&R[(long)row * ldC + col];
            float2 r1 = *(const float2*)&R[(long)(row + 8) * ldC + col];
            float2 o0, o1;
            o0.x = gm * acc[mi][ni][0] + r0.x;
            o0.y = gm * acc[mi][ni][1] + r0.y;
            o1.x = gm * acc[mi][ni][2] + r1.x;
            o1.y = gm * acc[mi][ni][3] + r1.y;
            *(float2*)&Cf[(long)row * ldC + col] = o0;
            *(float2*)&Cf[(long)(row + 8) * ldC + col] = o1;
        }
    }
}

// ===========================================================================
// kernel_launch  — inputs: x, Wf, bf, Wg, bg, Wh, bh, gamma
// ===========================================================================
extern "C" void kernel_launch(void* const* d_in, const int* in_sizes, int n_in,
                              void* d_out, int out_size)
{
    const float* x     = (const float*)d_in[0];
    const float* Wf    = (const float*)d_in[1];
    const float* bfp   = (const float*)d_in[2];
    const float* Wg    = (const float*)d_in[3];
    const float* bgp   = (const float*)d_in[4];
    const float* Wh    = (const float*)d_in[5];
    const float* bh    = (const float*)d_in[6];
    const float* gamma = (const float*)d_in[7];
    float* out = (float*)d_out;

    void *pxh, *pwfg, *pwh, *pbfg, *pfg, *pft, *ph, *pl, *pah;
    cudaGetSymbolAddress(&pxh,  d_xh);
    cudaGetSymbolAddress(&pwfg, d_Wfgh);
    cudaGetSymbolAddress(&pwh,  d_Whh);
    cudaGetSymbolAddress(&pbfg, d_bfg);
    cudaGetSymbolAddress(&pfg,  d_fgh);
    cudaGetSymbolAddress(&pft,  d_fTh);
    cudaGetSymbolAddress(&ph,   d_hvh);
    cudaGetSymbolAddress(&pl,   d_logits);
    cudaGetSymbolAddress(&pah,  d_attnh);
    __half* xh     = (__half*)pxh;
    __half* Wfgh   = (__half*)pwfg;
    __half* Whh    = (__half*)pwh;
    float*  bfg    = (float*)pbfg;
    __half* fgh    = (__half*)pfg;
    __half* fTh    = (__half*)pft;
    __half* hvh    = (__half*)ph;
    __half* logits = (__half*)pl;
    __half* attnh  = (__half*)pah;

    const long sx  = (long)NC * NTOK;
    const long sfg = (long)2 * NC8 * NTOK;
    const long sft = (long)NTOK * NC8;
    const long sat = (long)NTOK * NTOK;

    static cudaStream_t s2 = nullptr;
    static cudaEvent_t ev_fork = nullptr, ev_join = nullptr;
    static bool init_done = false;
    if (!init_done) {
        cudaFuncSetAttribute(gemm_mma<0>,
                             cudaFuncAttributeMaxDynamicSharedMemorySize, G_SMEM);
        cudaFuncSetAttribute(gemm_mma<1>,
                             cudaFuncAttributeMaxDynamicSharedMemorySize, G_SMEM);
        cudaFuncSetAttribute(gemm_mma_wide,
                             cudaFuncAttributeMaxDynamicSharedMemorySize, W_SMEM);
        cudaStreamCreateWithFlags(&s2, cudaStreamNonBlocking);
        cudaEventCreateWithFlags(&ev_fork, cudaEventDisableTiming);
        cudaEventCreateWithFlags(&ev_join, cudaEventDisableTiming);
        init_done = true;
    }

    // 0) conversions + bias pack (stream 0)
    convert_all<<<(unsigned)((CVT_TOTAL + 255) / 256), 256>>>(
        x, Wf, Wg, Wh, xh, Wfgh, Whh);
    pack_bias<<<1, 128>>>(bfp, bgp, bfg);

    // fork: hv projection runs on s2, overlapping the logits/softmax chain
    cudaEventRecord(ev_fork, 0);
    cudaStreamWaitEvent(s2, ev_fork, 0);

    // 1b) hv = Whh @ xh + bh   (stream s2)
    gemm_mma<0><<<dim3(NTOK / 128, NC / 128, BATCH), 256, G_SMEM, s2>>>(
        Whh, 0, NC, xh, sx, NTOK, hvh, sx, NTOK, bh, NC);
    cudaEventRecord(ev_join, s2);

    // 1) fg = Wfgh @ xh + bfg  (stream 0; rows 0-63 = f, 64-127 = g)
    gemm_mma<0><<<dim3(NTOK / 128, 1, BATCH), 256, G_SMEM>>>(
        Wfgh, 0, NC, xh, sx, NTOK, fgh, sfg, NTOK, bfg, NC);

    // 2) fT = transpose(f)
    transpose_f<<<dim3(NTOK / 64, 1, BATCH), 256>>>(fgh, sfg, fTh);

    // 3) logits = fT @ g  (fp16 out)
    gemm_mma<1><<<dim3(NTOK / 128, NTOK / 128, BATCH), 256, G_SMEM>>>(
        fTh, sft, NC8, fgh + (long)NC8 * NTOK, sfg, NTOK,
        logits, sat, NTOK, nullptr, NC8);

    // 4) softmax (fp16 -> fp16, fp32 math)
    softmax_rows<<<dim3(NTOK, BATCH), 256>>>(logits, attnh);

    // join hv before the final GEMM
    cudaStreamWaitEvent(0, ev_join, 0);

    // 5) out = gamma * (hvh @ attn) + x   (wide tile)
    gemm_mma_wide<<<dim3(NTOK / 256, NC / 128, BATCH), 512, W_SMEM>>>(
        hvh, sx, NTOK, attnh, sat, NTOK, out, sx, NTOK,
        x, sx, gamma, NTOK);
}